// round 1
// baseline (speedup 1.0000x reference)
#include <cuda_runtime.h>

#define NN 50000
#define NE 800000
#define DF 64
#define NF4 16          // DF/4
#define MPOLY 11
#define KD 4            // DEPTH+1

// ---------------- scratch (no allocations allowed) ----------------
__device__ float  g_deg[NN];
__device__ float  g_dinv[NN];
__device__ float  g_val[NE];
__device__ float4 g_y1[NN * NF4];
__device__ float4 g_y2[NN * NF4];
__device__ float4 g_y3[NN * NF4];
__device__ float  g_W[KD][KD];

// ---------------- zero scratch ----------------
__global__ void zero_all_kernel() {
    int i = blockIdx.x * blockDim.x + threadIdx.x;   // 800000 threads exactly
    float4 z = make_float4(0.f, 0.f, 0.f, 0.f);
    if (i < NN / 4) reinterpret_cast<float4*>(g_deg)[i] = z;
    g_y1[i] = z;
    g_y2[i] = z;
    g_y3[i] = z;
}

// ---------------- degree ----------------
__global__ void deg_kernel(const int* __restrict__ row) {
    int e = blockIdx.x * blockDim.x + threadIdx.x;
    if (e < NE) atomicAdd(&g_deg[row[e]], 1.0f);
}

__global__ void dinv_kernel() {
    int i = blockIdx.x * blockDim.x + threadIdx.x;
    if (i < NN) {
        float d = g_deg[i];
        if (d < 0.5f) d += 1.0f;
        g_dinv[i] = rsqrtf(d);
    }
}

__global__ void val_kernel(const int* __restrict__ row, const int* __restrict__ col,
                           const float* __restrict__ ea) {
    int e = blockIdx.x * blockDim.x + threadIdx.x;
    if (e < NE) g_val[e] = g_dinv[row[e]] * ea[e] * g_dinv[col[e]];
}

// ---------------- coefficient folding: c[k][m][j], W[k][j] = sum_m w[m]*c ----------------
// With L_INT=-1, R_INT=1: (l+r)/(r-l)=0, 2/(r-l)=1, so:
//   c1 = al0*((a-b)/2 * c0 + (a+b+2)/2 * shift(c0))
//   ck = tmp1*shift(c_{k-1}) - tmp2*c_{k-1} - tmp3*c_{k-2}
__global__ void coeff_kernel(const float* __restrict__ alphas, const float* __restrict__ w,
                             const float* __restrict__ a_arr, const float* __restrict__ b_arr) {
    if (blockIdx.x != 0 || threadIdx.x != 0) return;
    float W[KD][KD];
    for (int k = 0; k < KD; k++)
        for (int j = 0; j < KD; j++) W[k][j] = 0.f;

    for (int m = 0; m < MPOLY; m++) {
        float a = a_arr[m], b = b_arr[m];
        float c[KD][KD];
        for (int k = 0; k < KD; k++)
            for (int j = 0; j < KD; j++) c[k][j] = 0.f;
        c[0][0] = 1.f;

        float al0 = alphas[0 * MPOLY + m];
        c[1][0] = al0 * (a - b) * 0.5f;
        c[1][1] = al0 * (a + b + 2.f) * 0.5f;

        for (int L = 2; L <= 3; L++) {
            float Lf = (float)L;
            float s = a + b;
            float coef_l     = 2.f * Lf * (Lf + s) * (2.f * Lf - 2.f + s);
            float coef_lm1_1 = (2.f * Lf + s - 1.f) * (2.f * Lf + s) * (2.f * Lf + s - 2.f);
            float coef_lm1_2 = (2.f * Lf + s - 1.f) * (a * a - b * b);
            float coef_lm2   = 2.f * (Lf - 1.f + a) * (Lf - 1.f + b) * (2.f * Lf + s);
            float alL   = alphas[(L - 1) * MPOLY + m];
            float alLm1 = alphas[(L - 2) * MPOLY + m];
            float tmp1 = alL * (coef_lm1_1 / coef_l);
            float tmp2 = alL * (coef_lm1_2 / coef_l);
            float tmp3 = alL * alLm1 * (coef_lm2 / coef_l);
            for (int j = 0; j < KD; j++)
                c[L][j] = -tmp2 * c[L - 1][j] - tmp3 * c[L - 2][j];
            for (int j = 0; j < KD - 1; j++)
                c[L][j + 1] += tmp1 * c[L - 1][j];
        }
        float wm = w[m];
        for (int k = 0; k < KD; k++)
            for (int j = 0; j < KD; j++) W[k][j] += wm * c[k][j];
    }
    for (int k = 0; k < KD; k++)
        for (int j = 0; j < KD; j++) g_W[k][j] = W[k][j];
}

// ---------------- SpMM: y[row] += val * x[col], 16 threads/edge, float4 lanes ----------------
template <int STAGE>
__global__ void spmm_kernel(const int* __restrict__ row, const int* __restrict__ col,
                            const float4* __restrict__ xext) {
    int tid = blockIdx.x * blockDim.x + threadIdx.x;   // NE*16 threads exactly
    int e = tid >> 4;
    int f = tid & 15;
    const float4* xin = (STAGE == 1) ? xext
                      : (STAGE == 2) ? (const float4*)g_y1
                                     : (const float4*)g_y2;
    float4* yout = (STAGE == 1) ? g_y1 : (STAGE == 2) ? g_y2 : g_y3;

    int c = __ldg(&col[e]);
    int r = __ldg(&row[e]);
    float v = __ldg(&g_val[e]);
    float4 xv = __ldg(&xin[c * NF4 + f]);
    float4* dst = &yout[r * NF4 + f];
    asm volatile("red.global.add.v4.f32 [%0], {%1, %2, %3, %4};"
                 :: "l"(dst), "f"(v * xv.x), "f"(v * xv.y), "f"(v * xv.z), "f"(v * xv.w)
                 : "memory");
}

// ---------------- combine: out[n][k][d] = sum_j W[k][j] * (S^j x)[n][d] ----------------
__global__ void combine_kernel(const float4* __restrict__ x, float4* __restrict__ out) {
    int tid = blockIdx.x * blockDim.x + threadIdx.x;   // NN*16 threads exactly
    int n = tid >> 4;
    int f = tid & 15;
    int idx = n * NF4 + f;
    float4 h0 = __ldg(&x[idx]);
    float4 h1 = g_y1[idx];
    float4 h2 = g_y2[idx];
    float4 h3 = g_y3[idx];
#pragma unroll
    for (int k = 0; k < KD; k++) {
        float w0 = g_W[k][0], w1 = g_W[k][1], w2 = g_W[k][2], w3 = g_W[k][3];
        float4 o;
        o.x = w0 * h0.x + w1 * h1.x + w2 * h2.x + w3 * h3.x;
        o.y = w0 * h0.y + w1 * h1.y + w2 * h2.y + w3 * h3.y;
        o.z = w0 * h0.z + w1 * h1.z + w2 * h2.z + w3 * h3.z;
        o.w = w0 * h0.w + w1 * h1.w + w2 * h2.w + w3 * h3.w;
        out[(n * KD + k) * NF4 + f] = o;
    }
}

// ---------------- launch ----------------
extern "C" void kernel_launch(void* const* d_in, const int* in_sizes, int n_in,
                              void* d_out, int out_size) {
    const float* x      = (const float*)d_in[0];
    const int*   ei     = (const int*)d_in[1];
    const float* ea     = (const float*)d_in[2];
    const float* alphas = (const float*)d_in[3];
    const float* w      = (const float*)d_in[4];
    const float* a_arr  = (const float*)d_in[5];
    const float* b_arr  = (const float*)d_in[6];
    const int* row = ei;
    const int* col = ei + NE;

    zero_all_kernel<<<(NN * NF4) / 256, 256>>>();                    // 3125 blocks
    deg_kernel<<<(NE + 255) / 256, 256>>>(row);
    dinv_kernel<<<(NN + 255) / 256, 256>>>();
    val_kernel<<<(NE + 255) / 256, 256>>>(row, col, ea);
    coeff_kernel<<<1, 32>>>(alphas, w, a_arr, b_arr);

    const float4* x4 = (const float4*)x;
    spmm_kernel<1><<<(NE * 16) / 256, 256>>>(row, col, x4);          // 50000 blocks
    spmm_kernel<2><<<(NE * 16) / 256, 256>>>(row, col, x4);
    spmm_kernel<3><<<(NE * 16) / 256, 256>>>(row, col, x4);

    combine_kernel<<<(NN * NF4) / 256, 256>>>(x4, (float4*)d_out);
}